// round 7
// baseline (speedup 1.0000x reference)
#include <cuda_runtime.h>
#include <math.h>
#include <stdint.h>

#define MAXN 50048
#define MAXE 600064

// ---------------- scratch (static device globals; no allocation) ----------------
__device__ float g_b1[(size_t)MAXN * 128];   // hn -> attn (reused)
__device__ float g_Q [(size_t)MAXN * 128];   // Q -> y (reused)
__device__ float g_K [(size_t)MAXN * 128];   // K -> nf (reused)
__device__ float g_V [(size_t)MAXN * 128];
__device__ float g_x [(size_t)MAXN * 128];
__device__ float g_wV[(size_t)MAXN * 128];
__device__ float g_z [(size_t)MAXN * 4];
__device__ float g_t [(size_t)MAXN * 256];
__device__ float g_en[(size_t)MAXN];

__device__ __forceinline__ float clip5(float x) { return fminf(fmaxf(x, -5.f), 5.f); }
__device__ __forceinline__ float sigm(float x)  { return 1.f / (1.f + expf(-x)); }

__device__ __forceinline__ void red_add_v4(float* p, float a, float b, float c, float d) {
    asm volatile("red.global.add.v4.f32 [%0], {%1,%2,%3,%4};"
                 :: "l"(p), "f"(a), "f"(b), "f"(c), "f"(d) : "memory");
}
__device__ __forceinline__ void red_add_f(float* p, float v) {
    asm volatile("red.global.add.f32 [%0], %1;" :: "l"(p), "f"(v) : "memory");
}

// ---- 3xTF32 helpers ----
__device__ __forceinline__ void tf32split(float x, uint32_t& hi, uint32_t& lo) {
    uint32_t h; asm("cvt.rna.tf32.f32 %0, %1;" : "=r"(h) : "f"(x));
    float hf = __uint_as_float(h);
    float l = x - hf;
    uint32_t lr; asm("cvt.rna.tf32.f32 %0, %1;" : "=r"(lr) : "f"(l));
    hi = h; lo = lr;
}
__device__ __forceinline__ void mma8(float* d, const uint32_t* a, uint32_t b0, uint32_t b1) {
    asm volatile("mma.sync.aligned.m16n8k8.row.col.f32.tf32.tf32.f32 "
        "{%0,%1,%2,%3}, {%4,%5,%6,%7}, {%8,%9}, {%0,%1,%2,%3};"
        : "+f"(d[0]), "+f"(d[1]), "+f"(d[2]), "+f"(d[3])
        : "r"(a[0]), "r"(a[1]), "r"(a[2]), "r"(a[3]), "r"(b0), "r"(b1));
}

// ---------------- zero fill (wV and z in ONE launch) ----------------
__global__ void fzero2_kernel(float4* __restrict__ wv, float4* __restrict__ z,
                              int nwv4, int nz4) {
    int i = blockIdx.x * blockDim.x + threadIdx.x;
    if (i < nwv4) wv[i] = make_float4(0.f, 0.f, 0.f, 0.f);
    else {
        int j = i - nwv4;
        if (j < nz4) z[j] = make_float4(0.f, 0.f, 0.f, 0.f);
    }
}

// ---------------- row LayerNorm (warp per 128-wide row) ----------------
__global__ void ln_kernel(const float* __restrict__ in, float* __restrict__ out,
                          const float* __restrict__ w, const float* __restrict__ b, int rows) {
    int warp = (blockIdx.x * blockDim.x + threadIdx.x) >> 5;
    int lane = threadIdx.x & 31;
    if (warp >= rows) return;
    float4 v = *(const float4*)(in + (size_t)warp * 128 + 4 * lane);
    float s  = v.x + v.y + v.z + v.w;
    float sq = v.x * v.x + v.y * v.y + v.z * v.z + v.w * v.w;
#pragma unroll
    for (int o = 16; o; o >>= 1) {
        s  += __shfl_xor_sync(0xffffffffu, s,  o);
        sq += __shfl_xor_sync(0xffffffffu, sq, o);
    }
    float mu   = s * (1.f / 128.f);
    float rstd = rsqrtf(sq * (1.f / 128.f) - mu * mu + 1e-5f);
    float4 wv = *(const float4*)(w + 4 * lane);
    float4 bv = *(const float4*)(b + 4 * lane);
    float4 o4;
    o4.x = (v.x - mu) * rstd * wv.x + bv.x;
    o4.y = (v.y - mu) * rstd * wv.y + bv.y;
    o4.z = (v.z - mu) * rstd * wv.z + bv.z;
    o4.w = (v.w - mu) * rstd * wv.w + bv.w;
    *(float4*)(out + (size_t)warp * 128 + 4 * lane) = o4;
}

// ---------------- tensor GEMM body: tile 128x128, 3xTF32, split-at-load ----------------
// 8 warps = 4(m) x 2(n); warp tile 32x64.
// A_hi/A_lo [128][36] fp32 (tf32-rounded planes); W2 [32][136] float2 (hi,lo) pairs.
#define AS 36
#define WS2 136
template <int EPI>
__device__ __forceinline__ void gemm_body(
    const float* __restrict__ A, const float* __restrict__ W,
    const float* __restrict__ bias, const float* __restrict__ res,
    float* __restrict__ C, int M, int K, int NC, int row0, int cb,
    float* A_hi, float* A_lo, float2* W2) {
    int tid = threadIdx.x;
    int lane = tid & 31, wid = tid >> 5;
    int wm = wid >> 1, wn = wid & 1;
    int g = lane >> 2, t = lane & 3;
    float acc[2][8][4];
#pragma unroll
    for (int mf = 0; mf < 2; mf++)
#pragma unroll
        for (int nf = 0; nf < 8; nf++)
#pragma unroll
            for (int u = 0; u < 4; u++) acc[mf][nf][u] = 0.f;

    int nkt = K >> 5;
    float4 pa[4], pw[4];
#pragma unroll
    for (int it = 0; it < 4; ++it) {
        int idx = tid + it * 256;
        int r = idx >> 3, c4 = (idx & 7) << 2;
        pa[it] = make_float4(0.f, 0.f, 0.f, 0.f);
        if (row0 + r < M) pa[it] = *(const float4*)(A + (size_t)(row0 + r) * K + c4);
        int kk = idx >> 5, wc = (idx & 31) << 2;
        pw[it] = *(const float4*)(W + (size_t)kk * NC + cb + wc);
    }
    for (int kt = 0; kt < nkt; ++kt) {
        // stage: split into smem
#pragma unroll
        for (int it = 0; it < 4; ++it) {
            int idx = tid + it * 256;
            int r = idx >> 3, c4 = (idx & 7) << 2;
            uint32_t h, l; float4 hv, lv;
            tf32split(pa[it].x, h, l); hv.x = __uint_as_float(h); lv.x = __uint_as_float(l);
            tf32split(pa[it].y, h, l); hv.y = __uint_as_float(h); lv.y = __uint_as_float(l);
            tf32split(pa[it].z, h, l); hv.z = __uint_as_float(h); lv.z = __uint_as_float(l);
            tf32split(pa[it].w, h, l); hv.w = __uint_as_float(h); lv.w = __uint_as_float(l);
            *(float4*)(A_hi + r * AS + c4) = hv;
            *(float4*)(A_lo + r * AS + c4) = lv;
            int kk = idx >> 5, wc = (idx & 31) << 2;
            tf32split(pw[it].x, h, l); W2[kk * WS2 + wc + 0] = make_float2(__uint_as_float(h), __uint_as_float(l));
            tf32split(pw[it].y, h, l); W2[kk * WS2 + wc + 1] = make_float2(__uint_as_float(h), __uint_as_float(l));
            tf32split(pw[it].z, h, l); W2[kk * WS2 + wc + 2] = make_float2(__uint_as_float(h), __uint_as_float(l));
            tf32split(pw[it].w, h, l); W2[kk * WS2 + wc + 3] = make_float2(__uint_as_float(h), __uint_as_float(l));
        }
        __syncthreads();
        // prefetch next tile
        if (kt + 1 < nkt) {
#pragma unroll
            for (int it = 0; it < 4; ++it) {
                int idx = tid + it * 256;
                int r = idx >> 3, c4 = (idx & 7) << 2;
                pa[it] = make_float4(0.f, 0.f, 0.f, 0.f);
                if (row0 + r < M)
                    pa[it] = *(const float4*)(A + (size_t)(row0 + r) * K + (kt + 1) * 32 + c4);
                int kk = idx >> 5, wc = (idx & 31) << 2;
                pw[it] = *(const float4*)(W + (size_t)((kt + 1) * 32 + kk) * NC + cb + wc);
            }
        }
#pragma unroll
        for (int k8 = 0; k8 < 4; ++k8) {
            int ck = k8 * 8;
            uint32_t ahi[2][4], alo[2][4];
#pragma unroll
            for (int mf = 0; mf < 2; ++mf) {
                int rb = 32 * wm + 16 * mf;
                ahi[mf][0] = __float_as_uint(A_hi[(rb + g)     * AS + ck + t]);
                ahi[mf][1] = __float_as_uint(A_hi[(rb + g + 8) * AS + ck + t]);
                ahi[mf][2] = __float_as_uint(A_hi[(rb + g)     * AS + ck + t + 4]);
                ahi[mf][3] = __float_as_uint(A_hi[(rb + g + 8) * AS + ck + t + 4]);
                alo[mf][0] = __float_as_uint(A_lo[(rb + g)     * AS + ck + t]);
                alo[mf][1] = __float_as_uint(A_lo[(rb + g + 8) * AS + ck + t]);
                alo[mf][2] = __float_as_uint(A_lo[(rb + g)     * AS + ck + t + 4]);
                alo[mf][3] = __float_as_uint(A_lo[(rb + g + 8) * AS + ck + t + 4]);
            }
#pragma unroll
            for (int nf = 0; nf < 8; ++nf) {
                int nb = 64 * wn + 8 * nf + g;
                float2 p0 = W2[(ck + t)     * WS2 + nb];
                float2 p1 = W2[(ck + t + 4) * WS2 + nb];
                uint32_t bh0 = __float_as_uint(p0.x), bl0 = __float_as_uint(p0.y);
                uint32_t bh1 = __float_as_uint(p1.x), bl1 = __float_as_uint(p1.y);
#pragma unroll
                for (int mf = 0; mf < 2; ++mf) {
                    mma8(acc[mf][nf], alo[mf], bh0, bh1);
                    mma8(acc[mf][nf], ahi[mf], bl0, bl1);
                    mma8(acc[mf][nf], ahi[mf], bh0, bh1);
                }
            }
        }
        __syncthreads();
    }
    // epilogue
#pragma unroll
    for (int mf = 0; mf < 2; ++mf) {
#pragma unroll
        for (int nf = 0; nf < 8; ++nf) {
            int c  = cb + 64 * wn + 8 * nf + 2 * t;
            int r0 = row0 + 32 * wm + 16 * mf + g;
            float2 v0 = make_float2(acc[mf][nf][0], acc[mf][nf][1]);
            float2 v1 = make_float2(acc[mf][nf][2], acc[mf][nf][3]);
            if (EPI == 2) {
                v0.x = v0.x / (1.f + expf(-v0.x)); v0.y = v0.y / (1.f + expf(-v0.y));
                v1.x = v1.x / (1.f + expf(-v1.x)); v1.y = v1.y / (1.f + expf(-v1.y));
            }
            if (r0 < M) {
                if (EPI == 1) {
                    float2 b = *(const float2*)(bias + c);
                    float2 rr = *(const float2*)(res + (size_t)r0 * NC + c);
                    v0.x += b.x + rr.x; v0.y += b.y + rr.y;
                }
                if (EPI == 3) {
                    float2 rr = *(const float2*)(res + (size_t)r0 * NC + c);
                    v0.x += rr.x; v0.y += rr.y;
                }
                *(float2*)(C + (size_t)r0 * NC + c) = v0;
            }
            int r1 = r0 + 8;
            if (r1 < M) {
                if (EPI == 1) {
                    float2 b = *(const float2*)(bias + c);
                    float2 rr = *(const float2*)(res + (size_t)r1 * NC + c);
                    v1.x += b.x + rr.x; v1.y += b.y + rr.y;
                }
                if (EPI == 3) {
                    float2 rr = *(const float2*)(res + (size_t)r1 * NC + c);
                    v1.x += rr.x; v1.y += rr.y;
                }
                *(float2*)(C + (size_t)r1 * NC + c) = v1;
            }
        }
    }
}

#define GEMM_SMEM (2 * 128 * AS * 4 + 32 * WS2 * 8)

template <int EPI>
__global__ void __launch_bounds__(256, 2) gemm_kernel(
    const float* __restrict__ A, const float* __restrict__ W,
    const float* __restrict__ bias, const float* __restrict__ res,
    float* __restrict__ C, int M, int K, int NC) {
    extern __shared__ float gsh[];
    float* A_hi = gsh;
    float* A_lo = gsh + 128 * AS;
    float2* W2  = (float2*)(gsh + 2 * 128 * AS);
    gemm_body<EPI>(A, W, bias, res, C, M, K, NC, blockIdx.x * 128, blockIdx.y * 128,
                   A_hi, A_lo, W2);
}

__global__ void __launch_bounds__(256, 2) qkv_kernel(
    const float* __restrict__ A,
    const float* __restrict__ Wq, const float* __restrict__ Wk, const float* __restrict__ Wv,
    float* __restrict__ Q, float* __restrict__ Ko, float* __restrict__ V, int M) {
    extern __shared__ float gsh[];
    float* A_hi = gsh;
    float* A_lo = gsh + 128 * AS;
    float2* W2  = (float2*)(gsh + 2 * 128 * AS);
    const float* W = (blockIdx.y == 0) ? Wq : (blockIdx.y == 1) ? Wk : Wv;
    float* C       = (blockIdx.y == 0) ? Q  : (blockIdx.y == 1) ? Ko : V;
    gemm_body<0>(A, W, nullptr, nullptr, C, M, 128, 128, blockIdx.x * 128, 0, A_hi, A_lo, W2);
}

// ---------------- fused edge kernel: LN -> Pe GEMM (3xTF32) -> score/exp -> scatter ----
#define LN_STRIDE 132
__global__ void __launch_bounds__(256, 2) edge_kernel(
    const float* __restrict__ ef, const float* __restrict__ lnw, const float* __restrict__ lnb,
    const float* __restrict__ We, const int* __restrict__ src, const int* __restrict__ dst,
    const float* __restrict__ Q, const float* __restrict__ Kv, const float* __restrict__ V,
    float* __restrict__ wV, float* __restrict__ z, int E) {
    extern __shared__ float sh[];
    float* LN_sh = sh;                           // [128][132] fp32 (later Pe)
    float2* W2   = (float2*)(sh + 128 * LN_STRIDE);  // [32][136] (hi,lo)
    int* s_sh = (int*)(W2 + 32 * WS2);           // [128]
    int* d_sh = s_sh + 128;                      // [128]

    int tid = threadIdx.x, lane = tid & 31, w = tid >> 5;
    int e0 = blockIdx.x * 128;
    if (tid < 128) {
        int e = e0 + tid;
        s_sh[tid] = (e < E) ? src[e] : 0;
        d_sh[tid] = (e < E) ? dst[e] : 0;
    }
    float4 lw = *(const float4*)(lnw + 4 * lane);
    float4 lb = *(const float4*)(lnb + 4 * lane);
    // phase A: LN
#pragma unroll
    for (int i = 0; i < 16; i++) {
        int r = w * 16 + i;
        int e = e0 + r;
        float4 v = make_float4(0.f, 0.f, 0.f, 0.f);
        if (e < E) v = *(const float4*)(ef + (size_t)e * 128 + 4 * lane);
        float s  = v.x + v.y + v.z + v.w;
        float sq = v.x * v.x + v.y * v.y + v.z * v.z + v.w * v.w;
#pragma unroll
        for (int o = 16; o; o >>= 1) {
            s  += __shfl_xor_sync(0xffffffffu, s,  o);
            sq += __shfl_xor_sync(0xffffffffu, sq, o);
        }
        float mu   = s * (1.f / 128.f);
        float rstd = rsqrtf(sq * (1.f / 128.f) - mu * mu + 1e-5f);
        float4 o4;
        o4.x = (v.x - mu) * rstd * lw.x + lb.x;
        o4.y = (v.y - mu) * rstd * lw.y + lb.y;
        o4.z = (v.z - mu) * rstd * lw.z + lb.z;
        o4.w = (v.w - mu) * rstd * lw.w + lb.w;
        *(float4*)(LN_sh + r * LN_STRIDE + 4 * lane) = o4;
    }
    __syncthreads();
    // phase B: Pe = LN @ We via 3xTF32 (A split on-the-fly, B pairs in smem)
    int wm = w >> 1, wn = w & 1;
    int g = lane >> 2, t = lane & 3;
    float acc[2][8][4];
#pragma unroll
    for (int mf = 0; mf < 2; mf++)
#pragma unroll
        for (int nf = 0; nf < 8; nf++)
#pragma unroll
            for (int u = 0; u < 4; u++) acc[mf][nf][u] = 0.f;
    for (int kt = 0; kt < 4; ++kt) {
#pragma unroll
        for (int it = 0; it < 4; ++it) {
            int idx = tid + it * 256;
            int kk = idx >> 5, wc = (idx & 31) << 2;
            float4 v = *(const float4*)(We + (size_t)(kt * 32 + kk) * 128 + wc);
            uint32_t h, l;
            tf32split(v.x, h, l); W2[kk * WS2 + wc + 0] = make_float2(__uint_as_float(h), __uint_as_float(l));
            tf32split(v.y, h, l); W2[kk * WS2 + wc + 1] = make_float2(__uint_as_float(h), __uint_as_float(l));
            tf32split(v.z, h, l); W2[kk * WS2 + wc + 2] = make_float2(__uint_as_float(h), __uint_as_float(l));
            tf32split(v.w, h, l); W2[kk * WS2 + wc + 3] = make_float2(__uint_as_float(h), __uint_as_float(l));
        }
        __syncthreads();
#pragma unroll
        for (int k8 = 0; k8 < 4; ++k8) {
            int ckA = kt * 32 + k8 * 8;
            int ckW = k8 * 8;
            uint32_t ahi[2][4], alo[2][4];
#pragma unroll
            for (int mf = 0; mf < 2; ++mf) {
                int rb = 32 * wm + 16 * mf;
                float a0 = LN_sh[(rb + g)     * LN_STRIDE + ckA + t];
                float a1 = LN_sh[(rb + g + 8) * LN_STRIDE + ckA + t];
                float a2 = LN_sh[(rb + g)     * LN_STRIDE + ckA + t + 4];
                float a3 = LN_sh[(rb + g + 8) * LN_STRIDE + ckA + t + 4];
                tf32split(a0, ahi[mf][0], alo[mf][0]);
                tf32split(a1, ahi[mf][1], alo[mf][1]);
                tf32split(a2, ahi[mf][2], alo[mf][2]);
                tf32split(a3, ahi[mf][3], alo[mf][3]);
            }
#pragma unroll
            for (int nf = 0; nf < 8; ++nf) {
                int nb = 64 * wn + 8 * nf + g;
                float2 p0 = W2[(ckW + t)     * WS2 + nb];
                float2 p1 = W2[(ckW + t + 4) * WS2 + nb];
                uint32_t bh0 = __float_as_uint(p0.x), bl0 = __float_as_uint(p0.y);
                uint32_t bh1 = __float_as_uint(p1.x), bl1 = __float_as_uint(p1.y);
#pragma unroll
                for (int mf = 0; mf < 2; ++mf) {
                    mma8(acc[mf][nf], alo[mf], bh0, bh1);
                    mma8(acc[mf][nf], ahi[mf], bl0, bl1);
                    mma8(acc[mf][nf], ahi[mf], bh0, bh1);
                }
            }
        }
        __syncthreads();
    }
    // stash Pe into LN_sh
#pragma unroll
    for (int mf = 0; mf < 2; ++mf) {
#pragma unroll
        for (int nf = 0; nf < 8; ++nf) {
            int r0 = 32 * wm + 16 * mf + g;
            int c  = 64 * wn + 8 * nf + 2 * t;
            *(float2*)(LN_sh + r0 * LN_STRIDE + c)       = make_float2(acc[mf][nf][0], acc[mf][nf][1]);
            *(float2*)(LN_sh + (r0 + 8) * LN_STRIDE + c) = make_float2(acc[mf][nf][2], acc[mf][nf][3]);
        }
    }
    __syncthreads();
    // phase C: per-edge score, exp, scatter
    const float inv = 0.17677669529663687f;  // 1/sqrt(32)
    int head = lane >> 3;
    int base = w * 16;
    int si = s_sh[base], di = d_sh[base];
    float4 kq = *(const float4*)(Kv + (size_t)si * 128 + 4 * lane);
    float4 qv = *(const float4*)(Q  + (size_t)di * 128 + 4 * lane);
    float4 vv = *(const float4*)(V  + (size_t)si * 128 + 4 * lane);
#pragma unroll
    for (int j = 0; j < 16; j++) {
        int e = e0 + base + j;
        float4 kqc = kq, qvc = qv, vvc = vv;
        int dic = di;
        if (j < 15) {
            int sn = s_sh[base + j + 1], dn = d_sh[base + j + 1];
            kq = *(const float4*)(Kv + (size_t)sn * 128 + 4 * lane);
            qv = *(const float4*)(Q  + (size_t)dn * 128 + 4 * lane);
            vv = *(const float4*)(V  + (size_t)sn * 128 + 4 * lane);
            di = dn;
        }
        if (e < E) {
            float4 pe = *(float4*)(LN_sh + (base + j) * LN_STRIDE + 4 * lane);
            float tt = clip5(kqc.x * qvc.x * inv) * pe.x + clip5(kqc.y * qvc.y * inv) * pe.y
                     + clip5(kqc.z * qvc.z * inv) * pe.z + clip5(kqc.w * qvc.w * inv) * pe.w;
            tt += __shfl_xor_sync(0xffffffffu, tt, 1);
            tt += __shfl_xor_sync(0xffffffffu, tt, 2);
            tt += __shfl_xor_sync(0xffffffffu, tt, 4);
            float s = expf(clip5(tt));
            float* dp = wV + (size_t)dic * 128 + 4 * lane;
            red_add_v4(dp, vvc.x * s, vvc.y * s, vvc.z * s, vvc.w * s);
            if ((lane & 7) == 0) red_add_f(z + (size_t)dic * 4 + head, s);
        }
    }
}
#define EDGE_SMEM (128 * LN_STRIDE * 4 + 32 * WS2 * 8 + 2 * 128 * 4)

// ---------------- attn = wV / (z + 1e-6) ----------------
__global__ void attn_kernel(const float* __restrict__ wV, const float* __restrict__ z,
                            float* __restrict__ outp, int N) {
    int i = blockIdx.x * blockDim.x + threadIdx.x;
    if (i >= N * 32) return;
    int n = i >> 5;
    int head = (i & 31) >> 3;
    float invz = 1.f / (z[(size_t)n * 4 + head] + 1e-6f);
    float4 v = *(const float4*)(wV + (size_t)i * 4);
    v.x *= invz; v.y *= invz; v.z *= invz; v.w *= invz;
    *(float4*)(outp + (size_t)i * 4) = v;
}

// ---------------- Set2Set: one block per graph, all 3 iterations internal ----------------
__global__ void __launch_bounds__(256) set2set_kernel(
    const float* __restrict__ nf, const int* __restrict__ gid,
    const float* __restrict__ W_ih, const float* __restrict__ W_hh,
    const float* __restrict__ b_ih, const float* __restrict__ b_hh,
    float* __restrict__ ener, float* __restrict__ out, int N) {
    __shared__ float qs[256], hh[128], cc[128], gates[512], rsh[8 * 128], red[16];
    int tid = threadIdx.x, lane = tid & 31, w = tid >> 5;
    int g = blockIdx.x;
    int lo, hi;
    {
        int a = 0, b = N;
        while (a < b) { int m = (a + b) >> 1; if (gid[m] < g) a = m + 1; else b = m; }
        lo = a;
        b = N;
        while (a < b) { int m = (a + b) >> 1; if (gid[m] < g + 1) a = m + 1; else b = m; }
        hi = a;
    }
    qs[tid] = 0.f;
    if (tid < 128) { hh[tid] = 0.f; cc[tid] = 0.f; }
    __syncthreads();

    for (int it = 0; it < 3; ++it) {
        for (int j = tid; j < 512; j += 256) {
            float acc = b_ih[j] + b_hh[j];
            const float* wi = W_ih + (size_t)j * 256;
#pragma unroll 8
            for (int k2 = 0; k2 < 256; k2++) acc += qs[k2] * wi[k2];
            const float* whp = W_hh + (size_t)j * 128;
#pragma unroll 8
            for (int k2 = 0; k2 < 128; k2++) acc += hh[k2] * whp[k2];
            gates[j] = acc;
        }
        __syncthreads();
        if (tid < 128) {
            float c = sigm(gates[128 + tid]) * cc[tid] + sigm(gates[tid]) * tanhf(gates[256 + tid]);
            cc[tid] = c;
            hh[tid] = sigm(gates[384 + tid]) * tanhf(c);
        }
        __syncthreads();
        float mloc = -INFINITY;
        float4 h4 = *(float4*)&hh[4 * lane];
        for (int n = lo + w; n < hi; n += 8) {
            float4 a4 = *(const float4*)(nf + (size_t)n * 128 + 4 * lane);
            float t = a4.x * h4.x + a4.y * h4.y + a4.z * h4.z + a4.w * h4.w;
#pragma unroll
            for (int o = 16; o; o >>= 1) t += __shfl_xor_sync(0xffffffffu, t, o);
            if (lane == 0) ener[n] = t;
            mloc = fmaxf(mloc, t);
        }
#pragma unroll
        for (int o = 16; o; o >>= 1) mloc = fmaxf(mloc, __shfl_xor_sync(0xffffffffu, mloc, o));
        if (lane == 0) red[w] = mloc;
        __syncthreads();
        if (tid == 0) {
            float m = -INFINITY;
            for (int i = 0; i < 8; i++) m = fmaxf(m, red[i]);
            red[8] = m;
        }
        __syncthreads();
        float m = red[8];
        float dloc = 0.f;
        for (int n = lo + tid; n < hi; n += 256) dloc += expf(ener[n] - m);
#pragma unroll
        for (int o = 16; o; o >>= 1) dloc += __shfl_xor_sync(0xffffffffu, dloc, o);
        __syncthreads();
        if (lane == 0) red[w] = dloc;
        __syncthreads();
        if (tid == 0) {
            float d = 0.f;
            for (int i = 0; i < 8; i++) d += red[i];
            red[9] = d;
        }
        __syncthreads();
        float invd = 1.f / red[9];
        float4 racc = make_float4(0.f, 0.f, 0.f, 0.f);
        for (int n = lo + w; n < hi; n += 8) {
            float coef = expf(ener[n] - m) * invd;
            float4 a4 = *(const float4*)(nf + (size_t)n * 128 + 4 * lane);
            racc.x += coef * a4.x; racc.y += coef * a4.y;
            racc.z += coef * a4.z; racc.w += coef * a4.w;
        }
        *(float4*)&rsh[w * 128 + 4 * lane] = racc;
        __syncthreads();
        if (tid < 128) {
            float ro = 0.f;
#pragma unroll
            for (int i = 0; i < 8; i++) ro += rsh[i * 128 + tid];
            qs[tid] = hh[tid];
            qs[128 + tid] = ro;
        }
        __syncthreads();
    }
    out[(size_t)g * 256 + tid] = qs[tid];
}

// ---------------- launch ----------------
extern "C" void kernel_launch(void* const* d_in, const int* in_sizes, int n_in,
                              void* d_out, int out_size) {
    const float* node = (const float*)d_in[0];
    const float* edge = (const float*)d_in[1];
    const float* Wq = (const float*)d_in[2];
    const float* Wk = (const float*)d_in[3];
    const float* Wv = (const float*)d_in[4];
    const float* We = (const float*)d_in[5];
    const float* Wo = (const float*)d_in[6];
    const float* bo = (const float*)d_in[7];
    const float* W1 = (const float*)d_in[8];
    const float* W2 = (const float*)d_in[9];
    const float* l1nw = (const float*)d_in[10];
    const float* l1nb = (const float*)d_in[11];
    const float* l1ew = (const float*)d_in[12];
    const float* l1eb = (const float*)d_in[13];
    const float* l2w = (const float*)d_in[14];
    const float* l2b = (const float*)d_in[15];
    const float* Wih = (const float*)d_in[16];
    const float* Whh = (const float*)d_in[17];
    const float* bih = (const float*)d_in[18];
    const float* bhh = (const float*)d_in[19];
    const int* src = (const int*)d_in[20];
    const int* dst = (const int*)d_in[21];
    const int* gid = (const int*)d_in[22];

    int N = in_sizes[0] / 128;
    int E = in_sizes[20];
    int G = out_size / 256;

    float *b1, *q, *k, *v, *x, *wv, *z, *t, *en;
    cudaGetSymbolAddress((void**)&b1, g_b1);
    cudaGetSymbolAddress((void**)&q,  g_Q);
    cudaGetSymbolAddress((void**)&k,  g_K);
    cudaGetSymbolAddress((void**)&v,  g_V);
    cudaGetSymbolAddress((void**)&x,  g_x);
    cudaGetSymbolAddress((void**)&wv, g_wV);
    cudaGetSymbolAddress((void**)&z,  g_z);
    cudaGetSymbolAddress((void**)&t,  g_t);
    cudaGetSymbolAddress((void**)&en, g_en);

    cudaFuncSetAttribute(edge_kernel, cudaFuncAttributeMaxDynamicSharedMemorySize, EDGE_SMEM);
    cudaFuncSetAttribute(qkv_kernel, cudaFuncAttributeMaxDynamicSharedMemorySize, GEMM_SMEM);
    cudaFuncSetAttribute(gemm_kernel<1>, cudaFuncAttributeMaxDynamicSharedMemorySize, GEMM_SMEM);
    cudaFuncSetAttribute(gemm_kernel<2>, cudaFuncAttributeMaxDynamicSharedMemorySize, GEMM_SMEM);
    cudaFuncSetAttribute(gemm_kernel<3>, cudaFuncAttributeMaxDynamicSharedMemorySize, GEMM_SMEM);

    int gnodes = (N + 127) / 128;

    // launch order tuned so edge_kernel is app-launch #4 (ncu -s 5 with 2 harness
    // pre-launches -> captures edge_kernel)
    // 1) LN(node) -> b1
    ln_kernel<<<(N + 7) / 8, 256>>>(node, b1, l1nw, l1nb, N);
    // 2) Q, K, V
    qkv_kernel<<<dim3(gnodes, 3), 256, GEMM_SMEM>>>(b1, Wq, Wk, Wv, q, k, v, N);
    // 3) zero wV and z in one launch
    fzero2_kernel<<<(N * 33 + 255) / 256, 256>>>((float4*)wv, (float4*)z, N * 32, N);
    // 4) fused edge kernel
    edge_kernel<<<(E + 127) / 128, 256, EDGE_SMEM>>>(edge, l1ew, l1eb, We, src, dst,
                                                     q, k, v, wv, z, E);
    // 5) attn -> b1
    attn_kernel<<<(N * 32 + 255) / 256, 256>>>(wv, z, b1, N);
    // 6) x = node + attn@Wo + bo
    gemm_kernel<1><<<dim3(gnodes, 1), 256, GEMM_SMEM>>>(b1, Wo, bo, node, x, N, 128, 128);
    // 7) y = LN2(x) -> q
    ln_kernel<<<(N + 7) / 8, 256>>>(x, q, l2w, l2b, N);
    // 8) t = silu(y @ W1)
    gemm_kernel<2><<<dim3(gnodes, 2), 256, GEMM_SMEM>>>(q, W1, nullptr, nullptr, t, N, 128, 256);
    // 9) nf = x + t @ W2 -> k
    gemm_kernel<3><<<dim3(gnodes, 1), 256, GEMM_SMEM>>>(t, W2, nullptr, x, k, N, 256, 128);
    // 10) Set2Set readout
    set2set_kernel<<<G, 256>>>(k, gid, Wih, Whh, bih, bhh, en, (float*)d_out, N);
}

// round 10
// speedup vs baseline: 1.0639x; 1.0639x over previous
#include <cuda_runtime.h>
#include <math.h>
#include <stdint.h>

#define MAXN 50048
#define MAXE 600064

// ---------------- scratch (static device globals; no allocation) ----------------
__device__ float g_b1[(size_t)MAXN * 128];
__device__ float g_Q [(size_t)MAXN * 128];
__device__ float g_K [(size_t)MAXN * 128];
__device__ float g_V [(size_t)MAXN * 128];
__device__ float g_x [(size_t)MAXN * 128];
__device__ float g_wV[(size_t)MAXN * 128];
__device__ float g_z [(size_t)MAXN * 4];
__device__ float g_t [(size_t)MAXN * 256];   // FFN hidden; later reused as ener buffer
__device__ float g_s [(size_t)MAXE * 4];     // per-edge, per-head softmax numerators

__device__ __forceinline__ float clip5(float x) { return fminf(fmaxf(x, -5.f), 5.f); }
__device__ __forceinline__ float sigm(float x)  { return 1.f / (1.f + expf(-x)); }

__device__ __forceinline__ void red_add_v4(float* p, float a, float b, float c, float d) {
    asm volatile("red.global.add.v4.f32 [%0], {%1,%2,%3,%4};"
                 :: "l"(p), "f"(a), "f"(b), "f"(c), "f"(d) : "memory");
}
__device__ __forceinline__ void red_add_f(float* p, float v) {
    asm volatile("red.global.add.f32 [%0], %1;" :: "l"(p), "f"(v) : "memory");
}

// ---- 3xTF32 helpers ----
__device__ __forceinline__ void tf32split(float x, uint32_t& hi, uint32_t& lo) {
    uint32_t h; asm("cvt.rna.tf32.f32 %0, %1;" : "=r"(h) : "f"(x));
    float hf = __uint_as_float(h);
    float l = x - hf;
    uint32_t lr; asm("cvt.rna.tf32.f32 %0, %1;" : "=r"(lr) : "f"(l));
    hi = h; lo = lr;
}
__device__ __forceinline__ void mma8(float* d, const uint32_t* a, uint32_t b0, uint32_t b1) {
    asm volatile("mma.sync.aligned.m16n8k8.row.col.f32.tf32.tf32.f32 "
        "{%0,%1,%2,%3}, {%4,%5,%6,%7}, {%8,%9}, {%0,%1,%2,%3};"
        : "+f"(d[0]), "+f"(d[1]), "+f"(d[2]), "+f"(d[3])
        : "r"(a[0]), "r"(a[1]), "r"(a[2]), "r"(a[3]), "r"(b0), "r"(b1));
}

// ---------------- zero fill (wV and z in ONE launch) ----------------
__global__ void fzero2_kernel(float4* __restrict__ wv, float4* __restrict__ z,
                              int nwv4, int nz4) {
    int i = blockIdx.x * blockDim.x + threadIdx.x;
    if (i < nwv4) wv[i] = make_float4(0.f, 0.f, 0.f, 0.f);
    else {
        int j = i - nwv4;
        if (j < nz4) z[j] = make_float4(0.f, 0.f, 0.f, 0.f);
    }
}

// ---------------- row LayerNorm (warp per 128-wide row) ----------------
__global__ void ln_kernel(const float* __restrict__ in, float* __restrict__ out,
                          const float* __restrict__ w, const float* __restrict__ b, int rows) {
    int warp = (blockIdx.x * blockDim.x + threadIdx.x) >> 5;
    int lane = threadIdx.x & 31;
    if (warp >= rows) return;
    float4 v = *(const float4*)(in + (size_t)warp * 128 + 4 * lane);
    float s  = v.x + v.y + v.z + v.w;
    float sq = v.x * v.x + v.y * v.y + v.z * v.z + v.w * v.w;
#pragma unroll
    for (int o = 16; o; o >>= 1) {
        s  += __shfl_xor_sync(0xffffffffu, s,  o);
        sq += __shfl_xor_sync(0xffffffffu, sq, o);
    }
    float mu   = s * (1.f / 128.f);
    float rstd = rsqrtf(sq * (1.f / 128.f) - mu * mu + 1e-5f);
    float4 wv = *(const float4*)(w + 4 * lane);
    float4 bv = *(const float4*)(b + 4 * lane);
    float4 o4;
    o4.x = (v.x - mu) * rstd * wv.x + bv.x;
    o4.y = (v.y - mu) * rstd * wv.y + bv.y;
    o4.z = (v.z - mu) * rstd * wv.z + bv.z;
    o4.w = (v.w - mu) * rstd * wv.w + bv.w;
    *(float4*)(out + (size_t)warp * 128 + 4 * lane) = o4;
}

// ---------------- tensor-core GEMM body (R6-proven): 128x128, 3xTF32 ------------------
#define AS 36
#define WS 136
template <int EPI>
__device__ __forceinline__ void gemm_body(
    const float* __restrict__ A, const float* __restrict__ W,
    const float* __restrict__ bias, const float* __restrict__ res,
    float* __restrict__ C, int M, int K, int NC, int row0, int cb,
    float* A_sh, float* Whi, float* Wlo) {
    int tid = threadIdx.x;
    int lane = tid & 31, wid = tid >> 5;
    int wm = wid >> 1, wn = wid & 1;
    int g = lane >> 2, t = lane & 3;
    float acc[2][8][4];
#pragma unroll
    for (int mf = 0; mf < 2; mf++)
#pragma unroll
        for (int nf = 0; nf < 8; nf++)
#pragma unroll
            for (int u = 0; u < 4; u++) acc[mf][nf][u] = 0.f;

    int nkt = K >> 5;
    for (int kt = 0; kt < nkt; ++kt) {
#pragma unroll
        for (int it = 0; it < 4; ++it) {
            int idx = tid + it * 256;
            int r = idx >> 3, c4 = (idx & 7) << 2;
            float4 v = make_float4(0.f, 0.f, 0.f, 0.f);
            if (row0 + r < M) v = *(const float4*)(A + (size_t)(row0 + r) * K + kt * 32 + c4);
            *(float4*)(A_sh + r * AS + c4) = v;
        }
#pragma unroll
        for (int it = 0; it < 4; ++it) {
            int idx = tid + it * 256;
            int kk = idx >> 5, wc = (idx & 31) << 2;
            float4 v = *(const float4*)(W + (size_t)(kt * 32 + kk) * NC + cb + wc);
            uint32_t h, l; float4 hv, lv;
            tf32split(v.x, h, l); hv.x = __uint_as_float(h); lv.x = __uint_as_float(l);
            tf32split(v.y, h, l); hv.y = __uint_as_float(h); lv.y = __uint_as_float(l);
            tf32split(v.z, h, l); hv.z = __uint_as_float(h); lv.z = __uint_as_float(l);
            tf32split(v.w, h, l); hv.w = __uint_as_float(h); lv.w = __uint_as_float(l);
            *(float4*)(Whi + kk * WS + wc) = hv;
            *(float4*)(Wlo + kk * WS + wc) = lv;
        }
        __syncthreads();
#pragma unroll
        for (int k8 = 0; k8 < 4; ++k8) {
            int ck = k8 * 8;
            uint32_t ahi[2][4], alo[2][4];
#pragma unroll
            for (int mf = 0; mf < 2; ++mf) {
                int rb = 32 * wm + 16 * mf;
                float a0 = A_sh[(rb + g)     * AS + ck + t];
                float a1 = A_sh[(rb + g + 8) * AS + ck + t];
                float a2 = A_sh[(rb + g)     * AS + ck + t + 4];
                float a3 = A_sh[(rb + g + 8) * AS + ck + t + 4];
                tf32split(a0, ahi[mf][0], alo[mf][0]);
                tf32split(a1, ahi[mf][1], alo[mf][1]);
                tf32split(a2, ahi[mf][2], alo[mf][2]);
                tf32split(a3, ahi[mf][3], alo[mf][3]);
            }
#pragma unroll
            for (int nf = 0; nf < 8; ++nf) {
                int nb = 64 * wn + 8 * nf + g;
                uint32_t bh0 = __float_as_uint(Whi[(ck + t)     * WS + nb]);
                uint32_t bh1 = __float_as_uint(Whi[(ck + t + 4) * WS + nb]);
                uint32_t bl0 = __float_as_uint(Wlo[(ck + t)     * WS + nb]);
                uint32_t bl1 = __float_as_uint(Wlo[(ck + t + 4) * WS + nb]);
#pragma unroll
                for (int mf = 0; mf < 2; ++mf) {
                    mma8(acc[mf][nf], alo[mf], bh0, bh1);
                    mma8(acc[mf][nf], ahi[mf], bl0, bl1);
                    mma8(acc[mf][nf], ahi[mf], bh0, bh1);
                }
            }
        }
        __syncthreads();
    }
#pragma unroll
    for (int mf = 0; mf < 2; ++mf) {
#pragma unroll
        for (int nf = 0; nf < 8; ++nf) {
            int c  = cb + 64 * wn + 8 * nf + 2 * t;
            int r0 = row0 + 32 * wm + 16 * mf + g;
            float2 v0 = make_float2(acc[mf][nf][0], acc[mf][nf][1]);
            float2 v1 = make_float2(acc[mf][nf][2], acc[mf][nf][3]);
            if (EPI == 2) {
                v0.x = v0.x / (1.f + expf(-v0.x)); v0.y = v0.y / (1.f + expf(-v0.y));
                v1.x = v1.x / (1.f + expf(-v1.x)); v1.y = v1.y / (1.f + expf(-v1.y));
            }
            if (r0 < M) {
                if (EPI == 1) {
                    float2 b = *(const float2*)(bias + c);
                    float2 rr = *(const float2*)(res + (size_t)r0 * NC + c);
                    v0.x += b.x + rr.x; v0.y += b.y + rr.y;
                }
                if (EPI == 3) {
                    float2 rr = *(const float2*)(res + (size_t)r0 * NC + c);
                    v0.x += rr.x; v0.y += rr.y;
                }
                *(float2*)(C + (size_t)r0 * NC + c) = v0;
            }
            int r1 = r0 + 8;
            if (r1 < M) {
                if (EPI == 1) {
                    float2 b = *(const float2*)(bias + c);
                    float2 rr = *(const float2*)(res + (size_t)r1 * NC + c);
                    v1.x += b.x + rr.x; v1.y += b.y + rr.y;
                }
                if (EPI == 3) {
                    float2 rr = *(const float2*)(res + (size_t)r1 * NC + c);
                    v1.x += rr.x; v1.y += rr.y;
                }
                *(float2*)(C + (size_t)r1 * NC + c) = v1;
            }
        }
    }
}

#define GEMM_SMEM ((128 * AS + 2 * 32 * WS) * 4)

template <int EPI>
__global__ void __launch_bounds__(256, 2) gemm_kernel(
    const float* __restrict__ A, const float* __restrict__ W,
    const float* __restrict__ bias, const float* __restrict__ res,
    float* __restrict__ C, int M, int K, int NC) {
    extern __shared__ float gsh[];
    float* A_sh = gsh;
    float* Whi  = gsh + 128 * AS;
    float* Wlo  = Whi + 32 * WS;
    gemm_body<EPI>(A, W, bias, res, C, M, K, NC, blockIdx.x * 128, blockIdx.y * 128,
                   A_sh, Whi, Wlo);
}

__global__ void __launch_bounds__(256, 2) qkv_kernel(
    const float* __restrict__ A,
    const float* __restrict__ Wq, const float* __restrict__ Wk, const float* __restrict__ Wv,
    float* __restrict__ Q, float* __restrict__ Ko, float* __restrict__ V, int M) {
    extern __shared__ float gsh[];
    float* A_sh = gsh;
    float* Whi  = gsh + 128 * AS;
    float* Wlo  = Whi + 32 * WS;
    const float* W = (blockIdx.y == 0) ? Wq : (blockIdx.y == 1) ? Wk : Wv;
    float* C       = (blockIdx.y == 0) ? Q  : (blockIdx.y == 1) ? Ko : V;
    gemm_body<0>(A, W, nullptr, nullptr, C, M, 128, 128, blockIdx.x * 128, 0, A_sh, Whi, Wlo);
}

// ---------------- edge kernel: LN -> Pe GEMM (3xTF32) -> score/exp -> write s[E,4] ----
#define LN_STRIDE 132
__global__ void __launch_bounds__(256, 2) edge_kernel(
    const float* __restrict__ ef, const float* __restrict__ lnw, const float* __restrict__ lnb,
    const float* __restrict__ We, const int* __restrict__ src, const int* __restrict__ dst,
    const float* __restrict__ Q, const float* __restrict__ Kv,
    float* __restrict__ s_out, int E) {
    extern __shared__ float sh[];
    float* LN_sh = sh;
    float* Whi   = sh + 128 * LN_STRIDE;
    float* Wlo   = Whi + 32 * WS;
    int* s_sh = (int*)(Wlo + 32 * WS);
    int* d_sh = s_sh + 128;

    int tid = threadIdx.x, lane = tid & 31, w = tid >> 5;
    int e0 = blockIdx.x * 128;
    if (tid < 128) {
        int e = e0 + tid;
        s_sh[tid] = (e < E) ? src[e] : 0;
        d_sh[tid] = (e < E) ? dst[e] : 0;
    }
    float4 lw = *(const float4*)(lnw + 4 * lane);
    float4 lb = *(const float4*)(lnb + 4 * lane);
#pragma unroll
    for (int i = 0; i < 16; i++) {
        int r = w * 16 + i;
        int e = e0 + r;
        float4 v = make_float4(0.f, 0.f, 0.f, 0.f);
        if (e < E) v = *(const float4*)(ef + (size_t)e * 128 + 4 * lane);
        float s  = v.x + v.y + v.z + v.w;
        float sq = v.x * v.x + v.y * v.y + v.z * v.z + v.w * v.w;
#pragma unroll
        for (int o = 16; o; o >>= 1) {
            s  += __shfl_xor_sync(0xffffffffu, s,  o);
            sq += __shfl_xor_sync(0xffffffffu, sq, o);
        }
        float mu   = s * (1.f / 128.f);
        float rstd = rsqrtf(sq * (1.f / 128.f) - mu * mu + 1e-5f);
        float4 o4;
        o4.x = (v.x - mu) * rstd * lw.x + lb.x;
        o4.y = (v.y - mu) * rstd * lw.y + lb.y;
        o4.z = (v.z - mu) * rstd * lw.z + lb.z;
        o4.w = (v.w - mu) * rstd * lw.w + lb.w;
        *(float4*)(LN_sh + r * LN_STRIDE + 4 * lane) = o4;
    }
    __syncthreads();
    int wm = w >> 1, wn = w & 1;
    int g = lane >> 2, t = lane & 3;
    float acc[2][8][4];
#pragma unroll
    for (int mf = 0; mf < 2; mf++)
#pragma unroll
        for (int nf = 0; nf < 8; nf++)
#pragma unroll
            for (int u = 0; u < 4; u++) acc[mf][nf][u] = 0.f;
    for (int kt = 0; kt < 4; ++kt) {
#pragma unroll
        for (int it = 0; it < 4; ++it) {
            int idx = tid + it * 256;
            int kk = idx >> 5, wc = (idx & 31) << 2;
            float4 v = *(const float4*)(We + (size_t)(kt * 32 + kk) * 128 + wc);
            uint32_t h, l; float4 hv, lv;
            tf32split(v.x, h, l); hv.x = __uint_as_float(h); lv.x = __uint_as_float(l);
            tf32split(v.y, h, l); hv.y = __uint_as_float(h); lv.y = __uint_as_float(l);
            tf32split(v.z, h, l); hv.z = __uint_as_float(h); lv.z = __uint_as_float(l);
            tf32split(v.w, h, l); hv.w = __uint_as_float(h); lv.w = __uint_as_float(l);
            *(float4*)(Whi + kk * WS + wc) = hv;
            *(float4*)(Wlo + kk * WS + wc) = lv;
        }
        __syncthreads();
#pragma unroll
        for (int k8 = 0; k8 < 4; ++k8) {
            int ckA = kt * 32 + k8 * 8;
            int ckW = k8 * 8;
            uint32_t ahi[2][4], alo[2][4];
#pragma unroll
            for (int mf = 0; mf < 2; ++mf) {
                int rb = 32 * wm + 16 * mf;
                float a0 = LN_sh[(rb + g)     * LN_STRIDE + ckA + t];
                float a1 = LN_sh[(rb + g + 8) * LN_STRIDE + ckA + t];
                float a2 = LN_sh[(rb + g)     * LN_STRIDE + ckA + t + 4];
                float a3 = LN_sh[(rb + g + 8) * LN_STRIDE + ckA + t + 4];
                tf32split(a0, ahi[mf][0], alo[mf][0]);
                tf32split(a1, ahi[mf][1], alo[mf][1]);
                tf32split(a2, ahi[mf][2], alo[mf][2]);
                tf32split(a3, ahi[mf][3], alo[mf][3]);
            }
#pragma unroll
            for (int nf = 0; nf < 8; ++nf) {
                int nb = 64 * wn + 8 * nf + g;
                uint32_t bh0 = __float_as_uint(Whi[(ckW + t)     * WS + nb]);
                uint32_t bh1 = __float_as_uint(Whi[(ckW + t + 4) * WS + nb]);
                uint32_t bl0 = __float_as_uint(Wlo[(ckW + t)     * WS + nb]);
                uint32_t bl1 = __float_as_uint(Wlo[(ckW + t + 4) * WS + nb]);
#pragma unroll
                for (int mf = 0; mf < 2; ++mf) {
                    mma8(acc[mf][nf], alo[mf], bh0, bh1);
                    mma8(acc[mf][nf], ahi[mf], bl0, bl1);
                    mma8(acc[mf][nf], ahi[mf], bh0, bh1);
                }
            }
        }
        __syncthreads();
    }
#pragma unroll
    for (int mf = 0; mf < 2; ++mf) {
#pragma unroll
        for (int nf = 0; nf < 8; ++nf) {
            int r0 = 32 * wm + 16 * mf + g;
            int c  = 64 * wn + 8 * nf + 2 * t;
            *(float2*)(LN_sh + r0 * LN_STRIDE + c)       = make_float2(acc[mf][nf][0], acc[mf][nf][1]);
            *(float2*)(LN_sh + (r0 + 8) * LN_STRIDE + c) = make_float2(acc[mf][nf][2], acc[mf][nf][3]);
        }
    }
    __syncthreads();
    const float inv = 0.17677669529663687f;
    int head = lane >> 3;
    int base = w * 16;
    int si = s_sh[base], di = d_sh[base];
    float4 kq = *(const float4*)(Kv + (size_t)si * 128 + 4 * lane);
    float4 qv = *(const float4*)(Q  + (size_t)di * 128 + 4 * lane);
#pragma unroll
    for (int j = 0; j < 16; j++) {
        int e = e0 + base + j;
        float4 kqc = kq, qvc = qv;
        if (j < 15) {
            int sn = s_sh[base + j + 1], dn = d_sh[base + j + 1];
            kq = *(const float4*)(Kv + (size_t)sn * 128 + 4 * lane);
            qv = *(const float4*)(Q  + (size_t)dn * 128 + 4 * lane);
        }
        if (e < E) {
            float4 pe = *(float4*)(LN_sh + (base + j) * LN_STRIDE + 4 * lane);
            float tt = clip5(kqc.x * qvc.x * inv) * pe.x + clip5(kqc.y * qvc.y * inv) * pe.y
                     + clip5(kqc.z * qvc.z * inv) * pe.z + clip5(kqc.w * qvc.w * inv) * pe.w;
            tt += __shfl_xor_sync(0xffffffffu, tt, 1);
            tt += __shfl_xor_sync(0xffffffffu, tt, 2);
            tt += __shfl_xor_sync(0xffffffffu, tt, 4);
            float s = expf(clip5(tt));
            if ((lane & 7) == 0) s_out[(size_t)e * 4 + head] = s;
        }
    }
}
#define EDGE_SMEM ((128 * LN_STRIDE + 2 * 32 * WS) * 4 + 2 * 128 * 4)

// ---------------- scatter kernel: one warp per edge, high occupancy -------------------
__global__ void __launch_bounds__(256) scatter_kernel(
    const float* __restrict__ s, const int* __restrict__ src, const int* __restrict__ dst,
    const float* __restrict__ V, float* __restrict__ wV, float* __restrict__ z, int E) {
    int gw = (blockIdx.x * blockDim.x + threadIdx.x) >> 5;
    if (gw >= E) return;
    int lane = threadIdx.x & 31;
    int head = lane >> 3;
    int si = __ldg(src + gw), di = __ldg(dst + gw);
    float sv = __ldg(s + (size_t)gw * 4 + head);
    float4 vv = *(const float4*)(V + (size_t)si * 128 + 4 * lane);
    float* dp = wV + (size_t)di * 128 + 4 * lane;
    red_add_v4(dp, vv.x * sv, vv.y * sv, vv.z * sv, vv.w * sv);
    if ((lane & 7) == 0) red_add_f(z + (size_t)di * 4 + head, sv);
}

// ---------------- attn = wV / (z + 1e-6) ----------------
__global__ void attn_kernel(const float* __restrict__ wV, const float* __restrict__ z,
                            float* __restrict__ outp, int N) {
    int i = blockIdx.x * blockDim.x + threadIdx.x;
    if (i >= N * 32) return;
    int n = i >> 5;
    int head = (i & 31) >> 3;
    float invz = 1.f / (z[(size_t)n * 4 + head] + 1e-6f);
    float4 v = *(const float4*)(wV + (size_t)i * 4);
    v.x *= invz; v.y *= invz; v.z *= invz; v.w *= invz;
    *(float4*)(outp + (size_t)i * 4) = v;
}

// ---------------- Set2Set: one block per graph, all 3 iterations internal ----------------
__global__ void __launch_bounds__(256) set2set_kernel(
    const float* __restrict__ nf, const int* __restrict__ gid,
    const float* __restrict__ W_ih, const float* __restrict__ W_hh,
    const float* __restrict__ b_ih, const float* __restrict__ b_hh,
    float* __restrict__ ener, float* __restrict__ out, int N) {
    __shared__ float qs[256], hh[128], cc[128], gates[512], rsh[8 * 128], red[16];
    int tid = threadIdx.x, lane = tid & 31, w = tid >> 5;
    int g = blockIdx.x;
    int lo, hi;
    {
        int a = 0, b = N;
        while (a < b) { int m = (a + b) >> 1; if (gid[m] < g) a = m + 1; else b = m; }
        lo = a;
        b = N;
        while (a < b) { int m = (a + b) >> 1; if (gid[m] < g + 1) a = m + 1; else b = m; }
        hi = a;
    }
    qs[tid] = 0.f;
    if (tid < 128) { hh[tid] = 0.f; cc[tid] = 0.f; }
    __syncthreads();

    for (int it = 0; it < 3; ++it) {
        for (int j = tid; j < 512; j += 256) {
            float acc = b_ih[j] + b_hh[j];
            const float* wi = W_ih + (size_t)j * 256;
#pragma unroll 8
            for (int k2 = 0; k2 < 256; k2++) acc += qs[k2] * wi[k2];
            const float* whp = W_hh + (size_t)j * 128;
#pragma unroll 8
            for (int k2 = 0; k2 < 128; k2++) acc += hh[k2] * whp[k2];
            gates[j] = acc;
        }
        __syncthreads();
        if (tid < 128) {
            float c = sigm(gates[128 + tid]) * cc[tid] + sigm(gates[tid]) * tanhf(gates[256 + tid]);
            cc[tid] = c;
            hh[tid] = sigm(gates[384 + tid]) * tanhf(c);
        }
        __syncthreads();
        float mloc = -INFINITY;
        float4 h4 = *(float4*)&hh[4 * lane];
        for (int n = lo + w; n < hi; n += 8) {
            float4 a4 = *(const float4*)(nf + (size_t)n * 128 + 4 * lane);
            float t = a4.x * h4.x + a4.y * h4.y + a4.z * h4.z + a4.w * h4.w;
#pragma unroll
            for (int o = 16; o; o >>= 1) t += __shfl_xor_sync(0xffffffffu, t, o);
            if (lane == 0) ener[n] = t;
            mloc = fmaxf(mloc, t);
        }
#pragma unroll
        for (int o = 16; o; o >>= 1) mloc = fmaxf(mloc, __shfl_xor_sync(0xffffffffu, mloc, o));
        if (lane == 0) red[w] = mloc;
        __syncthreads();
        if (tid == 0) {
            float m = -INFINITY;
            for (int i = 0; i < 8; i++) m = fmaxf(m, red[i]);
            red[8] = m;
        }
        __syncthreads();
        float m = red[8];
        float dloc = 0.f;
        for (int n = lo + tid; n < hi; n += 256) dloc += expf(ener[n] - m);
#pragma unroll
        for (int o = 16; o; o >>= 1) dloc += __shfl_xor_sync(0xffffffffu, dloc, o);
        __syncthreads();
        if (lane == 0) red[w] = dloc;
        __syncthreads();
        if (tid == 0) {
            float d = 0.f;
            for (int i = 0; i < 8; i++) d += red[i];
            red[9] = d;
        }
        __syncthreads();
        float invd = 1.f / red[9];
        float4 racc = make_float4(0.f, 0.f, 0.f, 0.f);
        for (int n = lo + w; n < hi; n += 8) {
            float coef = expf(ener[n] - m) * invd;
            float4 a4 = *(const float4*)(nf + (size_t)n * 128 + 4 * lane);
            racc.x += coef * a4.x; racc.y += coef * a4.y;
            racc.z += coef * a4.z; racc.w += coef * a4.w;
        }
        *(float4*)&rsh[w * 128 + 4 * lane] = racc;
        __syncthreads();
        if (tid < 128) {
            float ro = 0.f;
#pragma unroll
            for (int i = 0; i < 8; i++) ro += rsh[i * 128 + tid];
            qs[tid] = hh[tid];
            qs[128 + tid] = ro;
        }
        __syncthreads();
    }
    out[(size_t)g * 256 + tid] = qs[tid];
}

// ---------------- launch ----------------
extern "C" void kernel_launch(void* const* d_in, const int* in_sizes, int n_in,
                              void* d_out, int out_size) {
    const float* node = (const float*)d_in[0];
    const float* edge = (const float*)d_in[1];
    const float* Wq = (const float*)d_in[2];
    const float* Wk = (const float*)d_in[3];
    const float* Wv = (const float*)d_in[4];
    const float* We = (const float*)d_in[5];
    const float* Wo = (const float*)d_in[6];
    const float* bo = (const float*)d_in[7];
    const float* W1 = (const float*)d_in[8];
    const float* W2 = (const float*)d_in[9];
    const float* l1nw = (const float*)d_in[10];
    const float* l1nb = (const float*)d_in[11];
    const float* l1ew = (const float*)d_in[12];
    const float* l1eb = (const float*)d_in[13];
    const float* l2w = (const float*)d_in[14];
    const float* l2b = (const float*)d_in[15];
    const float* Wih = (const float*)d_in[16];
    const float* Whh = (const float*)d_in[17];
    const float* bih = (const float*)d_in[18];
    const float* bhh = (const float*)d_in[19];
    const int* src = (const int*)d_in[20];
    const int* dst = (const int*)d_in[21];
    const int* gid = (const int*)d_in[22];

    int N = in_sizes[0] / 128;
    int E = in_sizes[20];
    int G = out_size / 256;

    float *b1, *q, *k, *v, *x, *wv, *z, *t, *sbuf;
    cudaGetSymbolAddress((void**)&b1, g_b1);
    cudaGetSymbolAddress((void**)&q,  g_Q);
    cudaGetSymbolAddress((void**)&k,  g_K);
    cudaGetSymbolAddress((void**)&v,  g_V);
    cudaGetSymbolAddress((void**)&x,  g_x);
    cudaGetSymbolAddress((void**)&wv, g_wV);
    cudaGetSymbolAddress((void**)&z,  g_z);
    cudaGetSymbolAddress((void**)&t,  g_t);
    cudaGetSymbolAddress((void**)&sbuf, g_s);

    cudaFuncSetAttribute(edge_kernel, cudaFuncAttributeMaxDynamicSharedMemorySize, EDGE_SMEM);
    cudaFuncSetAttribute(qkv_kernel, cudaFuncAttributeMaxDynamicSharedMemorySize, GEMM_SMEM);
    cudaFuncSetAttribute(gemm_kernel<1>, cudaFuncAttributeMaxDynamicSharedMemorySize, GEMM_SMEM);
    cudaFuncSetAttribute(gemm_kernel<2>, cudaFuncAttributeMaxDynamicSharedMemorySize, GEMM_SMEM);
    cudaFuncSetAttribute(gemm_kernel<3>, cudaFuncAttributeMaxDynamicSharedMemorySize, GEMM_SMEM);

    int gnodes = (N + 127) / 128;

    ln_kernel<<<(N + 7) / 8, 256>>>(node, b1, l1nw, l1nb, N);
    qkv_kernel<<<dim3(gnodes, 3), 256, GEMM_SMEM>>>(b1, Wq, Wk, Wv, q, k, v, N);
    fzero2_kernel<<<(N * 33 + 255) / 256, 256>>>((float4*)wv, (float4*)z, N * 32, N);
    edge_kernel<<<(E + 127) / 128, 256, EDGE_SMEM>>>(edge, l1ew, l1eb, We, src, dst,
                                                     q, k, sbuf, E);
    scatter_kernel<<<(E * 32 + 255) / 256, 256>>>(sbuf, src, dst, v, wv, z, E);
    attn_kernel<<<(N * 32 + 255) / 256, 256>>>(wv, z, b1, N);
    gemm_kernel<1><<<dim3(gnodes, 1), 256, GEMM_SMEM>>>(b1, Wo, bo, node, x, N, 128, 128);
    ln_kernel<<<(N + 7) / 8, 256>>>(x, q, l2w, l2b, N);
    gemm_kernel<2><<<dim3(gnodes, 2), 256, GEMM_SMEM>>>(q, W1, nullptr, nullptr, t, N, 128, 256);
    gemm_kernel<3><<<dim3(gnodes, 1), 256, GEMM_SMEM>>>(t, W2, nullptr, x, k, N, 256, 128);
    set2set_kernel<<<G, 256>>>(k, gid, Wih, Whh, bih, bhh, t, (float*)d_out, N);
}